// round 1
// baseline (speedup 1.0000x reference)
#include <cuda_runtime.h>
#include <math.h>

// Problem constants
#define BATCH 4
#define SEQ   512
#define DIM   512
#define NH    8
#define HD    64
#define NL    6
#define DFFN  2048
#define VOCAB 32000
#define ROWS  (BATCH*SEQ)   // 2048

// ---------------- scratch (device globals; no allocation allowed) ----------
__device__ float g_x  [BATCH*SEQ*DIM];        // decoder / current activations
__device__ float g_enc[BATCH*SEQ*DIM];        // encoder activations / output
__device__ float g_q  [BATCH*SEQ*DIM];
__device__ float g_k  [BATCH*SEQ*DIM];
__device__ float g_v  [BATCH*SEQ*DIM];
__device__ float g_att[BATCH*SEQ*DIM];
__device__ float g_t  [BATCH*SEQ*DIM];        // GEMM staging before LN
__device__ float g_ffn[BATCH*SEQ*DFFN];
__device__ float g_sc [BATCH*NH*SEQ*SEQ];     // attention scores/probs

// ---------------- embedding + positional encoding ---------------------------
// Faithful to reference: fp64 angle = s / 10000^(2 d / 512); row 0 and col 0 -> 0;
// even d -> sin, odd d -> cos.
__global__ void k_embed(const int* __restrict__ tok, const float* __restrict__ emb,
                        float* __restrict__ out) {
    int idx = blockIdx.x * blockDim.x + threadIdx.x;   // < BATCH*SEQ*DIM
    int d  = idx & (DIM - 1);
    int bs = idx >> 9;                 // b*SEQ + s
    int s  = bs & (SEQ - 1);
    float pe = 0.f;
    if (s > 0 && d > 0) {
        double ang = (double)s / pow(10000.0, 2.0 * (double)d / (double)DIM);
        pe = (float)((d & 1) ? cos(ang) : sin(ang));
    }
    int t = tok[bs];
    out[idx] = emb[(size_t)t * DIM + d] + pe;
}

// ---------------- generic SGEMM: C = act(A@B + bias) ------------------------
// A: MxK row-major, B: KxN row-major, C: MxN.  M%64==0, N%64==0, K%16==0.
// act: 0 = none, 1 = leaky_relu(0.01)
__global__ void k_sgemm(int M, int N, int K,
                        const float* __restrict__ A, const float* __restrict__ B,
                        float* __restrict__ C, const float* __restrict__ bias, int act) {
    __shared__ float As[16][65];
    __shared__ float Bs[16][64];
    int tid  = threadIdx.x;              // 256 threads
    int row0 = blockIdx.y * 64;
    int col0 = blockIdx.x * 64;
    int tr   = (tid >> 4) << 2;          // 0..60
    int tc   = (tid & 15) << 2;          // 0..60
    float acc[4][4] = {};

    for (int k0 = 0; k0 < K; k0 += 16) {
#pragma unroll
        for (int i = 0; i < 4; i++) {
            int idx = tid + i * 256;          // 0..1023
            int m = idx >> 4, kk = idx & 15;
            As[kk][m] = A[(size_t)(row0 + m) * K + k0 + kk];
        }
#pragma unroll
        for (int i = 0; i < 4; i++) {
            int idx = tid + i * 256;
            int kk = idx >> 6, n = idx & 63;
            Bs[kk][n] = B[(size_t)(k0 + kk) * N + col0 + n];
        }
        __syncthreads();
#pragma unroll
        for (int kk = 0; kk < 16; kk++) {
            float a[4], b[4];
#pragma unroll
            for (int i = 0; i < 4; i++) a[i] = As[kk][tr + i];
#pragma unroll
            for (int j = 0; j < 4; j++) b[j] = Bs[kk][tc + j];
#pragma unroll
            for (int i = 0; i < 4; i++)
#pragma unroll
                for (int j = 0; j < 4; j++)
                    acc[i][j] = fmaf(a[i], b[j], acc[i][j]);
        }
        __syncthreads();
    }
#pragma unroll
    for (int i = 0; i < 4; i++) {
        int m = row0 + tr + i;
#pragma unroll
        for (int j = 0; j < 4; j++) {
            int n = col0 + tc + j;
            float v = acc[i][j];
            if (bias) v += bias[n];
            if (act) v = v > 0.f ? v : 0.01f * v;
            C[(size_t)m * N + n] = v;
        }
    }
}

// ---------------- attention scores: SC[b,h,q,k] = mask ? 1e-9 : (q.k)/8 -----
// grid (SEQ/64, SEQ/64, BATCH*NH), block 256
__global__ void k_scores(const float* __restrict__ Q, const float* __restrict__ Km,
                         const int* __restrict__ tok, int causal,
                         float* __restrict__ SC) {
    __shared__ float Qs[64][65];
    __shared__ float Ks[64][65];
    int z = blockIdx.z;                 // b*NH + h
    int b = z >> 3, h = z & 7;
    int q0 = blockIdx.y * 64, k0 = blockIdx.x * 64;
    int tid = threadIdx.x;
#pragma unroll
    for (int i = 0; i < 16; i++) {
        int idx = tid + i * 256;        // 0..4095
        int r = idx >> 6, d = idx & 63;
        Qs[r][d] = Q[((size_t)(b * SEQ) + q0 + r) * DIM + h * HD + d];
        Ks[r][d] = Km[((size_t)(b * SEQ) + k0 + r) * DIM + h * HD + d];
    }
    __syncthreads();
    int tr = (tid >> 4) << 2, tc = (tid & 15) << 2;
    float acc[4][4] = {};
#pragma unroll
    for (int d = 0; d < 64; d++) {
        float a[4], bb[4];
#pragma unroll
        for (int i = 0; i < 4; i++) a[i] = Qs[tr + i][d];
#pragma unroll
        for (int j = 0; j < 4; j++) bb[j] = Ks[tc + j][d];
#pragma unroll
        for (int i = 0; i < 4; i++)
#pragma unroll
            for (int j = 0; j < 4; j++)
                acc[i][j] = fmaf(a[i], bb[j], acc[i][j]);
    }
    float* out = SC + (size_t)z * SEQ * SEQ;
#pragma unroll
    for (int j = 0; j < 4; j++) {
        int k = k0 + tc + j;
        bool kmask = (tok[b * SEQ + k] == 0);
#pragma unroll
        for (int i = 0; i < 4; i++) {
            int q = q0 + tr + i;
            bool msk = kmask || (causal && k > q);
            out[(size_t)q * SEQ + k] = msk ? 1e-9f : acc[i][j] * 0.125f;
        }
    }
}

// ---------------- softmax over last dim (rows of 512) -----------------------
__global__ void k_softmax(float* __restrict__ SC) {
    int row = blockIdx.x;
    float* p = SC + (size_t)row * SEQ;
    __shared__ float red[256];
    int tid = threadIdx.x;
    float v0 = p[tid], v1 = p[tid + 256];
    red[tid] = fmaxf(v0, v1);
    __syncthreads();
    for (int s = 128; s > 0; s >>= 1) {
        if (tid < s) red[tid] = fmaxf(red[tid], red[tid + s]);
        __syncthreads();
    }
    float m = red[0];
    __syncthreads();
    float e0 = expf(v0 - m), e1 = expf(v1 - m);
    red[tid] = e0 + e1;
    __syncthreads();
    for (int s = 128; s > 0; s >>= 1) {
        if (tid < s) red[tid] += red[tid + s];
        __syncthreads();
    }
    float inv = 1.f / red[0];
    p[tid] = e0 * inv;
    p[tid + 256] = e1 * inv;
}

// ---------------- AV: O[b,q,h*64+d] = sum_k P[b,h,q,k] * V[b,k,h*64+d] ------
// grid (1, SEQ/64, BATCH*NH), block 256
__global__ void k_av(const float* __restrict__ P, const float* __restrict__ V,
                     float* __restrict__ O) {
    __shared__ float As[16][65];
    __shared__ float Bs[16][64];
    int z = blockIdx.z;
    int b = z >> 3, h = z & 7;
    int q0 = blockIdx.y * 64;
    int tid = threadIdx.x;
    int tr = (tid >> 4) << 2, tc = (tid & 15) << 2;
    float acc[4][4] = {};
    const float* Pz = P + (size_t)z * SEQ * SEQ;
    for (int k0 = 0; k0 < SEQ; k0 += 16) {
#pragma unroll
        for (int i = 0; i < 4; i++) {
            int idx = tid + i * 256;
            int m = idx >> 4, kk = idx & 15;
            As[kk][m] = Pz[(size_t)(q0 + m) * SEQ + k0 + kk];
        }
#pragma unroll
        for (int i = 0; i < 4; i++) {
            int idx = tid + i * 256;
            int kk = idx >> 6, n = idx & 63;
            Bs[kk][n] = V[((size_t)(b * SEQ) + k0 + kk) * DIM + h * HD + n];
        }
        __syncthreads();
#pragma unroll
        for (int kk = 0; kk < 16; kk++) {
            float a[4], bb[4];
#pragma unroll
            for (int i = 0; i < 4; i++) a[i] = As[kk][tr + i];
#pragma unroll
            for (int j = 0; j < 4; j++) bb[j] = Bs[kk][tc + j];
#pragma unroll
            for (int i = 0; i < 4; i++)
#pragma unroll
                for (int j = 0; j < 4; j++)
                    acc[i][j] = fmaf(a[i], bb[j], acc[i][j]);
        }
        __syncthreads();
    }
#pragma unroll
    for (int i = 0; i < 4; i++)
#pragma unroll
        for (int j = 0; j < 4; j++)
            O[((size_t)(b * SEQ) + q0 + tr + i) * DIM + h * HD + tc + j] = acc[i][j];
}

// ---------------- residual + LayerNorm: out = LN(t + r) * g + b -------------
// one block (256 threads) per row of 512
__global__ void k_lnres(const float* __restrict__ t, const float* __restrict__ r,
                        const float* __restrict__ g, const float* __restrict__ be,
                        float* __restrict__ out) {
    int row = blockIdx.x, tid = threadIdx.x;
    __shared__ float red[256];
    const float* tp = t + (size_t)row * DIM;
    const float* rp = r + (size_t)row * DIM;
    float a = tp[tid] + rp[tid];
    float b2 = tp[tid + 256] + rp[tid + 256];
    red[tid] = a + b2;
    __syncthreads();
    for (int s = 128; s > 0; s >>= 1) {
        if (tid < s) red[tid] += red[tid + s];
        __syncthreads();
    }
    float mean = red[0] * (1.f / DIM);
    __syncthreads();
    float da = a - mean, db = b2 - mean;
    red[tid] = da * da + db * db;
    __syncthreads();
    for (int s = 128; s > 0; s >>= 1) {
        if (tid < s) red[tid] += red[tid + s];
        __syncthreads();
    }
    float inv = 1.f / sqrtf(red[0] * (1.f / DIM) + 1e-6f);
    out[(size_t)row * DIM + tid]       = da * inv * g[tid] + be[tid];
    out[(size_t)row * DIM + tid + 256] = db * inv * g[tid + 256] + be[tid + 256];
}

// ---------------- host orchestration ---------------------------------------
static void mhsa(const float* xq, const float* xkv, const int* tok, int causal,
                 const float* Wq, const float* Wk, const float* Wv, const float* Wo,
                 const float* g1, const float* b1,
                 float* q, float* k, float* v, float* sc, float* att, float* t,
                 float* xout) {
    dim3 gP(DIM / 64, ROWS / 64);  // (8, 32)
    k_sgemm<<<gP, 256>>>(ROWS, DIM, DIM, xq,  Wq, q, nullptr, 0);
    k_sgemm<<<gP, 256>>>(ROWS, DIM, DIM, xkv, Wk, k, nullptr, 0);
    k_sgemm<<<gP, 256>>>(ROWS, DIM, DIM, xkv, Wv, v, nullptr, 0);
    k_scores<<<dim3(SEQ / 64, SEQ / 64, BATCH * NH), 256>>>(q, k, tok, causal, sc);
    k_softmax<<<BATCH * NH * SEQ, 256>>>(sc);
    k_av<<<dim3(1, SEQ / 64, BATCH * NH), 256>>>(sc, v, att);
    k_sgemm<<<gP, 256>>>(ROWS, DIM, DIM, att, Wo, t, nullptr, 0);
    k_lnres<<<ROWS, 256>>>(t, xq, g1, b1, xout);
}

static void ffn(float* xio, const float* W1, const float* c1,
                const float* W2, const float* c2, const float* g2, const float* b2,
                float* hbuf, float* t) {
    k_sgemm<<<dim3(DFFN / 64, ROWS / 64), 256>>>(ROWS, DFFN, DIM, xio, W1, hbuf, c1, 1);
    k_sgemm<<<dim3(DIM / 64, ROWS / 64), 256>>>(ROWS, DIM, DFFN, hbuf, W2, t, c2, 0);
    k_lnres<<<ROWS, 256>>>(t, xio, g2, b2, xio);
}

extern "C" void kernel_launch(void* const* d_in, const int* in_sizes, int n_in,
                              void* d_out, int out_size) {
    const int*   enc_tok = (const int*)d_in[0];
    const int*   dec_tok = (const int*)d_in[1];
    const float* emb_enc = (const float*)d_in[2];
    const float* emb_dec = (const float*)d_in[3];
    const float* projW   = (const float*)d_in[4];
    const float* ep[12];
    const float* dp[12];
    for (int i = 0; i < 12; i++) { ep[i] = (const float*)d_in[5 + i]; dp[i] = (const float*)d_in[17 + i]; }

    float *x, *enc, *q, *k, *v, *att, *t, *hffn, *sc;
    cudaGetSymbolAddress((void**)&x,    g_x);
    cudaGetSymbolAddress((void**)&enc,  g_enc);
    cudaGetSymbolAddress((void**)&q,    g_q);
    cudaGetSymbolAddress((void**)&k,    g_k);
    cudaGetSymbolAddress((void**)&v,    g_v);
    cudaGetSymbolAddress((void**)&att,  g_att);
    cudaGetSymbolAddress((void**)&t,    g_t);
    cudaGetSymbolAddress((void**)&hffn, g_ffn);
    cudaGetSymbolAddress((void**)&sc,   g_sc);

    const size_t wQ = (size_t)DIM * DIM;      // per-layer stride for Wq/Wk/Wv/Wo
    const size_t w1 = (size_t)DIM * DFFN;     // W1 and W2 per-layer stride
    // param index: 0 Wq, 1 Wk, 2 Wv, 3 Wo, 4 g1, 5 b1, 6 W1, 7 c1, 8 W2, 9 c2, 10 g2, 11 b2

    // ---- encoder ----
    k_embed<<<(BATCH * SEQ * DIM) / 256, 256>>>(enc_tok, emb_enc, enc);
    for (int l = 0; l < NL; l++) {
        mhsa(enc, enc, enc_tok, 0,
             ep[0] + l * wQ, ep[1] + l * wQ, ep[2] + l * wQ, ep[3] + l * wQ,
             ep[4] + l * DIM, ep[5] + l * DIM,
             q, k, v, sc, att, t, enc);
        ffn(enc, ep[6] + l * w1, ep[7] + l * DFFN, ep[8] + l * w1,
            ep[9] + l * DIM, ep[10] + l * DIM, ep[11] + l * DIM, hffn, t);
    }

    // ---- decoder ----
    k_embed<<<(BATCH * SEQ * DIM) / 256, 256>>>(dec_tok, emb_dec, x);
    for (int l = 0; l < NL; l++) {
        // self-attention (causal + pad mask on decoder tokens)
        mhsa(x, x, dec_tok, 1,
             dp[0] + l * wQ, dp[1] + l * wQ, dp[2] + l * wQ, dp[3] + l * wQ,
             dp[4] + l * DIM, dp[5] + l * DIM,
             q, k, v, sc, att, t, x);
        // cross-attention (same weights, kv = encoder output, encoder pad mask)
        mhsa(x, enc, enc_tok, 0,
             dp[0] + l * wQ, dp[1] + l * wQ, dp[2] + l * wQ, dp[3] + l * wQ,
             dp[4] + l * DIM, dp[5] + l * DIM,
             q, k, v, sc, att, t, x);
        ffn(x, dp[6] + l * w1, dp[7] + l * DFFN, dp[8] + l * w1,
            dp[9] + l * DIM, dp[10] + l * DIM, dp[11] + l * DIM, hffn, t);
    }

    // ---- final vocab projection: [2048,512] @ [512,32000] ----
    k_sgemm<<<dim3(VOCAB / 64, ROWS / 64), 256>>>(ROWS, VOCAB, DIM, x, projW,
                                                  (float*)d_out, nullptr, 0);
}